// round 4
// baseline (speedup 1.0000x reference)
#include <cuda_runtime.h>

typedef unsigned long long ull;

constexpr int BS = 16384, D = 100, H = 16, P = 2;
constexpr int TB_B = 64;      // batch per block
constexpr int TB_T = 8;       // t per block
constexpr int NTH  = 256;     // 8 warps
constexpr int JP   = 104;     // padded j / t extent
constexpr int NSTG = 13;      // j-stages of 8
constexpr int W0S  = 1668;    // sW0 row stride (104*16 + 4)
constexpr int W1S  = 260;

// sM stage geometry (floats/words)
constexpr int SM_C  = 260;            // c-stride (64*4 + 4 pad)
constexpr int SM_J  = 2 * SM_C;       // 520 per j
constexpr int SM_ST = 8 * SM_J;       // 4160 per stage
// smem map (float offsets)
constexpr int OFF_M  = 0;
constexpr int OFF_W0 = OFF_M  + 4 * SM_ST;       // 16640
constexpr int OFF_X  = OFF_W0 + 8 * W0S;         // 29984
constexpr int OFF_W1 = OFF_X  + JP * 64;         // 36640
constexpr int OFF_B1 = OFF_W1 + 8 * W1S;         // 38720
constexpr int OFF_W2 = OFF_B1 + 144;             // 38864
constexpr int OFF_B2 = OFF_W2 + 8 * 36;          // 39152
constexpr int SMEM_FLOATS = OFF_B2 + 16;         // 39168 -> 156672 B

__device__ float g_W0T[JP * JP * H];  // [t][j][i], zero-padded t,j >= 100
__device__ float g_xT[D * BS];        // [j][b]

__global__ void transpose_w0_kernel(const float* __restrict__ W0) {
    int t = blockIdx.x;  // 0..103
    for (int e = threadIdx.x; e < JP * H; e += blockDim.x) {
        int j = e >> 4, i = e & 15;
        float v = (t < D && j < D) ? W0[(t * H + i) * D + j] : 0.f;
        g_W0T[t * (JP * H) + e] = v;
    }
}

__global__ void transpose_x_kernel(const float* __restrict__ x) {
    __shared__ float tile[32][33];
    int bb = blockIdx.x * 32, jb = blockIdx.y * 32;
    int tx = threadIdx.x, ty = threadIdx.y;
    for (int r = ty; r < 32; r += 8) {
        int j = jb + tx;
        tile[r][tx] = (j < D) ? x[(bb + r) * D + j] : 0.f;
    }
    __syncthreads();
    for (int r = ty; r < 32; r += 8) {
        int j = jb + r;
        if (j < D) g_xT[j * BS + bb + tx] = tile[tx][r];
    }
}

__device__ __forceinline__ ull pk2(float a, float b) {
    ull r; asm("mov.b64 %0, {%1, %2};" : "=l"(r) : "f"(a), "f"(b)); return r;
}
__device__ __forceinline__ void unpk2(ull v, float& a, float& b) {
    asm("mov.b64 {%0, %1}, %2;" : "=f"(a), "=f"(b) : "l"(v));
}
__device__ __forceinline__ ull ffma2(ull a, ull b, ull c) {
    ull d; asm("fma.rn.f32x2 %0, %1, %2, %3;" : "=l"(d) : "l"(a), "l"(b), "l"(c));
    return d;
}
__device__ __forceinline__ float lrelu(float v) { return v > 0.f ? v : 0.01f * v; }
__device__ __forceinline__ unsigned smem_u32(const void* p) {
    unsigned a;
    asm("{ .reg .u64 t; cvta.to.shared.u64 t, %1; cvt.u32.u64 %0, t; }" : "=r"(a) : "l"(p));
    return a;
}

__global__ void __launch_bounds__(NTH, 1)
mlp_kernel(const float* __restrict__ M, const float* __restrict__ W1g,
           const float* __restrict__ W2g, const float* __restrict__ b0g,
           const float* __restrict__ b1g, const float* __restrict__ b2g,
           float* __restrict__ out) {
    extern __shared__ float smem[];
    float* sW0 = smem + OFF_W0;
    float* sX  = smem + OFF_X;
    float* sW1 = smem + OFF_W1;
    float* sB1 = smem + OFF_B1;
    float* sW2 = smem + OFF_W2;
    float* sB2 = smem + OFF_B2;
    const unsigned sM_base = smem_u32(smem);

    const int tid  = threadIdx.x;
    const int lane = tid & 31, w = tid >> 5;
    const int tl = lane & 7, bq = lane >> 3;
    const int t0 = blockIdx.y * TB_T;
    const int t  = t0 + tl;
    const bool tv = (t < D);
    const int Bb   = blockIdx.x * TB_B;
    const int bloc = w * 8 + bq * 2;          // thread's local b, b+1

    const int moff = (tl >> 2) * SM_C + bloc * 4 + (tl & 3);

    // ---- stage W0 / x / W1 / b1 / W2 / b2 ----
    for (int e = tid; e < 8 * (JP * H / 4); e += NTH) {          // 8 x 416 float4
        int r = e / 416, c = e - r * 416;
        float4 v = *((const float4*)(g_W0T + (t0 + r) * (JP * H)) + c);
        ((float4*)(sW0 + r * W0S))[c] = v;
    }
    for (int e = tid; e < JP * 16; e += NTH) {                   // 104 j x 16 float4
        int j = e >> 4, c = e & 15;
        float4 v = make_float4(0.f, 0.f, 0.f, 0.f);
        if (j < D) v = *((const float4*)(g_xT + (size_t)j * BS + Bb) + c);
        ((float4*)(sX + j * 64))[c] = v;
    }
    // W1: DIRECT copy (row-major [t][i][j]); consumer reads W1[t][ii][0..15].
    for (int e = tid; e < 8 * 256; e += NTH) {
        int r = e >> 8, c = e & 255;
        sW1[r * W1S + c] = (t0 + r < D) ? W1g[(t0 + r) * 256 + c] : 0.f;
    }
    if (tid < 128) {
        int r = tid >> 4, c = tid & 15;
        sB1[r * 17 + c] = (t0 + r < D) ? b1g[(t0 + r) * H + c] : 0.f;
    }
    if (tid < 256) {
        int r = tid >> 5, c = tid & 31;
        sW2[r * 36 + c] = (t0 + r < D) ? W2g[(t0 + r) * (P * H) + c] : 0.f;
    }
    if (tid < 16) {
        int r = tid >> 1, c = tid & 1;
        sB2[r * 2 + c] = (t0 + r < D) ? b2g[(t0 + r) * P + c] : 0.f;
    }

    // ---- async pipeline for M ----
#define ISSUE_STAGE(sidx)                                                        \
    {                                                                            \
        const int buf = (sidx) & 3;                                              \
        const int jc  = (sidx) * 8;                                              \
        _Pragma("unroll")                                                        \
        for (int k = 0; k < 4; ++k) {                                            \
            int e = tid + k * NTH;                                               \
            int c = e & 1, b = (e >> 1) & 63, jj = e >> 7;                       \
            int j = jc + jj;                                                     \
            bool ok = (j < D) && (t0 + c * 4 < D);                               \
            const float* src = ok                                                \
                ? M + ((size_t)(Bb + b) * D + j) * D + t0 + c * 4                \
                : M;                                                             \
            unsigned sz = ok ? 16u : 0u;                                         \
            unsigned dst = sM_base +                                             \
                ((unsigned)(buf * SM_ST + jj * SM_J + c * SM_C + b * 4) << 2);   \
            asm volatile("cp.async.cg.shared.global [%0], [%1], 16, %2;"         \
                         :: "r"(dst), "l"(src), "r"(sz));                        \
        }                                                                        \
        asm volatile("cp.async.commit_group;" ::: "memory");                     \
    }

    ISSUE_STAGE(0); ISSUE_STAGE(1); ISSUE_STAGE(2);

    // ---- acc init with b0 ----
    ull acc[2][8];
#pragma unroll
    for (int ip = 0; ip < 8; ++ip) {
        float a = tv ? __ldg(b0g + t * H + 2 * ip)     : 0.f;
        float b = tv ? __ldg(b0g + t * H + 2 * ip + 1) : 0.f;
        ull bb = pk2(a, b);
        acc[0][ip] = bb; acc[1][ip] = bb;
    }

#pragma unroll 1
    for (int s = 0; s < NSTG; ++s) {
        asm volatile("cp.async.wait_group 2;" ::: "memory");
        __syncthreads();
        const float* mbuf = smem + (s & 3) * SM_ST;
        const int jc = s * 8;
#pragma unroll
        for (int jj = 0; jj < 8; ++jj) {
            const int j = jc + jj;
            const float* mj = mbuf + jj * SM_J + moff;
            float m0 = mj[0], m1 = mj[4];
            float2 x2 = *(const float2*)(sX + j * 64 + bloc);
            const longlong2* wr = (const longlong2*)(sW0 + tl * W0S + j * 16);
            longlong2 q0 = wr[0], q1 = wr[1], q2 = wr[2], q3 = wr[3];
            ull W[8] = {(ull)q0.x, (ull)q0.y, (ull)q1.x, (ull)q1.y,
                        (ull)q2.x, (ull)q2.y, (ull)q3.x, (ull)q3.y};
            float mx0 = m0 * x2.x, mx1 = m1 * x2.y;
            ull p0 = pk2(mx0, mx0), p1 = pk2(mx1, mx1);
#pragma unroll
            for (int ip = 0; ip < 8; ++ip) {
                acc[0][ip] = ffma2(W[ip], p0, acc[0][ip]);
                acc[1][ip] = ffma2(W[ip], p1, acc[1][ip]);
            }
        }
        if (s + 3 < NSTG) {
            ISSUE_STAGE(s + 3);
        } else {
            asm volatile("cp.async.commit_group;" ::: "memory");
        }
    }
#undef ISSUE_STAGE

    // ---- diagonal correction: subtract j == t term ----
    if (tv) {
#pragma unroll
        for (int k = 0; k < 2; ++k) {
            int bgl = Bb + bloc + k;
            float md = __ldg(M + ((size_t)bgl * D + t) * D + t);
            float mx = md * sX[t * 64 + bloc + k];
            ull pm = pk2(-mx, -mx);
            const longlong2* wr = (const longlong2*)(sW0 + tl * W0S + t * 16);
            longlong2 q0 = wr[0], q1 = wr[1], q2 = wr[2], q3 = wr[3];
            ull W[8] = {(ull)q0.x, (ull)q0.y, (ull)q1.x, (ull)q1.y,
                        (ull)q2.x, (ull)q2.y, (ull)q3.x, (ull)q3.y};
#pragma unroll
            for (int ip = 0; ip < 8; ++ip) acc[k][ip] = ffma2(W[ip], pm, acc[k][ip]);
        }
    }

    // ---- layers 1 & 2 ----
#pragma unroll
    for (int k = 0; k < 2; ++k) {
        float h0f[16];
#pragma unroll
        for (int ip = 0; ip < 8; ++ip) {
            float a, b; unpk2(acc[k][ip], a, b);
            h0f[2 * ip]     = lrelu(a);
            h0f[2 * ip + 1] = lrelu(b);
        }
        float h1[16];
#pragma unroll
        for (int ii = 0; ii < 16; ++ii) {
            const float4* w1r = (const float4*)(sW1 + tl * W1S + ii * 16);
            float4 a = w1r[0], b = w1r[1], c = w1r[2], d = w1r[3];
            float s = sB1[tl * 17 + ii];
            s = fmaf(a.x, h0f[0],  s); s = fmaf(a.y, h0f[1],  s);
            s = fmaf(a.z, h0f[2],  s); s = fmaf(a.w, h0f[3],  s);
            s = fmaf(b.x, h0f[4],  s); s = fmaf(b.y, h0f[5],  s);
            s = fmaf(b.z, h0f[6],  s); s = fmaf(b.w, h0f[7],  s);
            s = fmaf(c.x, h0f[8],  s); s = fmaf(c.y, h0f[9],  s);
            s = fmaf(c.z, h0f[10], s); s = fmaf(c.w, h0f[11], s);
            s = fmaf(d.x, h0f[12], s); s = fmaf(d.y, h0f[13], s);
            s = fmaf(d.z, h0f[14], s); s = fmaf(d.w, h0f[15], s);
            h1[ii] = lrelu(s);
        }
        float po[2];
#pragma unroll
        for (int p = 0; p < 2; ++p) {
            const float4* w2r = (const float4*)(sW2 + tl * 36 + p * 16);
            float4 a = w2r[0], b = w2r[1], c = w2r[2], d = w2r[3];
            float s = sB2[tl * 2 + p];
            s = fmaf(a.x, h1[0],  s); s = fmaf(a.y, h1[1],  s);
            s = fmaf(a.z, h1[2],  s); s = fmaf(a.w, h1[3],  s);
            s = fmaf(b.x, h1[4],  s); s = fmaf(b.y, h1[5],  s);
            s = fmaf(b.z, h1[6],  s); s = fmaf(b.w, h1[7],  s);
            s = fmaf(c.x, h1[8],  s); s = fmaf(c.y, h1[9],  s);
            s = fmaf(c.z, h1[10], s); s = fmaf(c.w, h1[11], s);
            s = fmaf(d.x, h1[12], s); s = fmaf(d.y, h1[13], s);
            s = fmaf(d.z, h1[14], s); s = fmaf(d.w, h1[15], s);
            po[p] = s;
        }
        if (tv) {
            float2 o = make_float2(po[0], po[1]);
            *(float2*)(out + ((size_t)(Bb + bloc + k) * D + t) * P) = o;
        }
    }
}

extern "C" void kernel_launch(void* const* d_in, const int* in_sizes, int n_in,
                              void* d_out, int out_size) {
    const float* x  = (const float*)d_in[0];
    const float* M  = (const float*)d_in[1];
    const float* W0 = (const float*)d_in[2];
    const float* W1 = (const float*)d_in[3];
    const float* W2 = (const float*)d_in[4];
    const float* b0 = (const float*)d_in[5];
    const float* b1 = (const float*)d_in[6];
    const float* b2 = (const float*)d_in[7];
    float* out = (float*)d_out;

    constexpr int SMEM_BYTES = SMEM_FLOATS * 4;
    cudaFuncSetAttribute(mlp_kernel, cudaFuncAttributeMaxDynamicSharedMemorySize,
                         SMEM_BYTES);

    transpose_w0_kernel<<<JP, 256>>>(W0);
    transpose_x_kernel<<<dim3(BS / 32, (D + 31) / 32), dim3(32, 8)>>>(x);

    dim3 grid(BS / TB_B, (D + TB_T - 1) / TB_T);   // 256 x 13
    mlp_kernel<<<grid, NTH, SMEM_BYTES>>>(M, W1, W2, b0, b1, b2, out);
}

// round 6
// speedup vs baseline: 1.6171x; 1.6171x over previous
#include <cuda_runtime.h>

typedef unsigned long long ull;

constexpr int BS = 16384, D = 100, H = 16, P = 2;
constexpr int TB_B = 64;      // batch per block
constexpr int TB_T = 8;       // t per block
constexpr int NTH  = 256;     // 8 warps
constexpr int JP   = 104;     // padded j / t extent
constexpr int W0S  = 1668;    // sW0 row stride in floats (417 float4: 416 data + 1 pad)
constexpr int W1S  = 260;

// smem map (float offsets)
constexpr int OFF_W0 = 0;                       // 8 * 1668 = 13344
constexpr int OFF_X  = OFF_W0 + 8 * W0S;        // 13344 ; 104*64 = 6656
constexpr int OFF_W1 = OFF_X  + JP * 64;        // 20000 ; 8*260 = 2080
constexpr int OFF_B1 = OFF_W1 + 8 * W1S;        // 22080 ; 8*17 + pad
constexpr int OFF_W2 = OFF_B1 + 144;            // 22224 ; 8*36 = 288
constexpr int OFF_B2 = OFF_W2 + 8 * 36;         // 22512 ; 16
constexpr int SMEM_FLOATS = OFF_B2 + 16;        // 22528 -> 90112 B  (x2 CTA = 180224)

__device__ float g_W0T[JP * JP * H];  // [t][j][i], zero-padded t,j >= 100
__device__ float g_xT[D * BS];        // [j][b]

__global__ void transpose_w0_kernel(const float* __restrict__ W0) {
    int t = blockIdx.x;  // 0..103
    for (int e = threadIdx.x; e < JP * H; e += blockDim.x) {
        int j = e >> 4, i = e & 15;
        float v = (t < D && j < D) ? W0[(t * H + i) * D + j] : 0.f;
        g_W0T[t * (JP * H) + e] = v;
    }
}

__global__ void transpose_x_kernel(const float* __restrict__ x) {
    __shared__ float tile[32][33];
    int bb = blockIdx.x * 32, jb = blockIdx.y * 32;
    int tx = threadIdx.x, ty = threadIdx.y;
    for (int r = ty; r < 32; r += 8) {
        int j = jb + tx;
        tile[r][tx] = (j < D) ? x[(bb + r) * D + j] : 0.f;
    }
    __syncthreads();
    for (int r = ty; r < 32; r += 8) {
        int j = jb + r;
        if (j < D) g_xT[j * BS + bb + tx] = tile[tx][r];
    }
}

__device__ __forceinline__ ull pk2(float a, float b) {
    ull r; asm("mov.b64 %0, {%1, %2};" : "=l"(r) : "f"(a), "f"(b)); return r;
}
__device__ __forceinline__ void unpk2(ull v, float& a, float& b) {
    asm("mov.b64 {%0, %1}, %2;" : "=f"(a), "=f"(b) : "l"(v));
}
__device__ __forceinline__ ull ffma2(ull a, ull b, ull c) {
    ull d; asm("fma.rn.f32x2 %0, %1, %2, %3;" : "=l"(d) : "l"(a), "l"(b), "l"(c));
    return d;
}
__device__ __forceinline__ float lrelu(float v) { return v > 0.f ? v : 0.01f * v; }

__global__ void __launch_bounds__(NTH, 2)
mlp_kernel(const float* __restrict__ M, const float* __restrict__ W1g,
           const float* __restrict__ W2g, const float* __restrict__ b0g,
           const float* __restrict__ b1g, const float* __restrict__ b2g,
           float* __restrict__ out) {
    extern __shared__ float smem[];
    float* sW0 = smem + OFF_W0;
    float* sX  = smem + OFF_X;
    float* sW1 = smem + OFF_W1;
    float* sB1 = smem + OFF_B1;
    float* sW2 = smem + OFF_W2;
    float* sB2 = smem + OFF_B2;

    const int tid  = threadIdx.x;
    const int lane = tid & 31, w = tid >> 5;
    const int tl = lane & 7, bq = lane >> 3;
    const int t0 = blockIdx.y * TB_T;
    const int t  = t0 + tl;
    const bool tv = (t < D);
    const int tc = tv ? t : (D - 1);          // clamp: invalid lanes read valid dup
    const int Bb   = blockIdx.x * TB_B;
    const int bloc = w * 8 + bq * 2;          // thread's local b, b+1
    const int Bbase = Bb + bloc;

    // ---- stage W0 / x / W1 / b1 / W2 / b2 ----
    for (int e = tid; e < 8 * 416; e += NTH) {               // W0: 8 rows x 416 float4
        int r = e / 416, c = e - r * 416;
        float4 v = *((const float4*)(g_W0T + (t0 + r) * (JP * H)) + c);
        ((float4*)(sW0 + r * W0S))[c] = v;
    }
    for (int e = tid; e < JP * 16; e += NTH) {               // x: 104 j x 16 float4
        int j = e >> 4, c = e & 15;
        float4 v = make_float4(0.f, 0.f, 0.f, 0.f);
        if (j < D) v = *((const float4*)(g_xT + (size_t)j * BS + Bb) + c);
        ((float4*)(sX + j * 64))[c] = v;
    }
    for (int e = tid; e < 8 * 256; e += NTH) {               // W1: DIRECT copy
        int r = e >> 8, c = e & 255;
        sW1[r * W1S + c] = (t0 + r < D) ? W1g[(t0 + r) * 256 + c] : 0.f;
    }
    if (tid < 128) {
        int r = tid >> 4, c = tid & 15;
        sB1[r * 17 + c] = (t0 + r < D) ? b1g[(t0 + r) * H + c] : 0.f;
    }
    if (tid < 256) {
        int r = tid >> 5, c = tid & 31;
        sW2[r * 36 + c] = (t0 + r < D) ? W2g[(t0 + r) * (P * H) + c] : 0.f;
    }
    if (tid < 16) {
        int r = tid >> 1, c = tid & 1;
        sB2[r * 2 + c] = (t0 + r < D) ? b2g[(t0 + r) * P + c] : 0.f;
    }
    __syncthreads();

    // ---- acc init with b0 ----
    ull acc[2][8];
#pragma unroll
    for (int ip = 0; ip < 8; ++ip) {
        float a = tv ? __ldg(b0g + t * H + 2 * ip)     : 0.f;
        float b = tv ? __ldg(b0g + t * H + 2 * ip + 1) : 0.f;
        ull bb = pk2(a, b);
        acc[0][ip] = bb; acc[1][ip] = bb;
    }

    const float* mp = M + (size_t)Bbase * (D * D) + tc;  // + j*D (+ D*D for b+1)

    // 3-buffer register pipeline for M, chunk = 4 j, prefetch distance = 2 chunks
    float m[3][2][4];

#define LOAD_CHUNK(cn, buf)                                                     \
    if ((cn) < 25) {                                                            \
        _Pragma("unroll")                                                       \
        for (int u = 0; u < 4; ++u) {                                           \
            int j = (cn) * 4 + u;                                               \
            m[buf][0][u] = __ldg(mp + j * D);                                   \
            m[buf][1][u] = __ldg(mp + j * D + D * D);                           \
        }                                                                       \
    }

#define COMP_CHUNK(cn, buf)                                                     \
    {                                                                           \
        _Pragma("unroll")                                                       \
        for (int u = 0; u < 4; ++u) {                                           \
            int j = (cn) * 4 + u;                                               \
            float2 x2 = *(const float2*)(sX + j * 64 + bloc);                   \
            const longlong2* wr = (const longlong2*)(sW0 + tl * W0S + j * 16);  \
            longlong2 q0 = wr[0], q1 = wr[1], q2 = wr[2], q3 = wr[3];           \
            ull W[8] = {(ull)q0.x, (ull)q0.y, (ull)q1.x, (ull)q1.y,             \
                        (ull)q2.x, (ull)q2.y, (ull)q3.x, (ull)q3.y};            \
            float mx0 = m[buf][0][u] * x2.x, mx1 = m[buf][1][u] * x2.y;         \
            ull p0 = pk2(mx0, mx0), p1 = pk2(mx1, mx1);                         \
            _Pragma("unroll")                                                   \
            for (int ip = 0; ip < 8; ++ip) {                                    \
                acc[0][ip] = ffma2(W[ip], p0, acc[0][ip]);                      \
                acc[1][ip] = ffma2(W[ip], p1, acc[1][ip]);                      \
            }                                                                   \
        }                                                                       \
    }

    LOAD_CHUNK(0, 0);
    LOAD_CHUNK(1, 1);
#pragma unroll 1
    for (int kb = 0; kb < 24; kb += 3) {
        LOAD_CHUNK(kb + 2, 2); COMP_CHUNK(kb, 0);
        LOAD_CHUNK(kb + 3, 0); COMP_CHUNK(kb + 1, 1);
        LOAD_CHUNK(kb + 4, 1); COMP_CHUNK(kb + 2, 2);
    }
    COMP_CHUNK(24, 0);
#undef LOAD_CHUNK
#undef COMP_CHUNK

    // ---- diagonal correction: subtract j == t term ----
    if (tv) {
#pragma unroll
        for (int k = 0; k < 2; ++k) {
            float md = __ldg(M + ((size_t)(Bbase + k) * D + t) * D + t);
            float mx = md * sX[t * 64 + bloc + k];
            ull pm = pk2(-mx, -mx);
            const longlong2* wr = (const longlong2*)(sW0 + tl * W0S + t * 16);
            longlong2 q0 = wr[0], q1 = wr[1], q2 = wr[2], q3 = wr[3];
            ull W[8] = {(ull)q0.x, (ull)q0.y, (ull)q1.x, (ull)q1.y,
                        (ull)q2.x, (ull)q2.y, (ull)q3.x, (ull)q3.y};
#pragma unroll
            for (int ip = 0; ip < 8; ++ip) acc[k][ip] = ffma2(W[ip], pm, acc[k][ip]);
        }
    }

    // ---- layers 1 & 2 ----
#pragma unroll
    for (int k = 0; k < 2; ++k) {
        float h0f[16];
#pragma unroll
        for (int ip = 0; ip < 8; ++ip) {
            float a, b; unpk2(acc[k][ip], a, b);
            h0f[2 * ip]     = lrelu(a);
            h0f[2 * ip + 1] = lrelu(b);
        }
        float h1[16];
#pragma unroll
        for (int ii = 0; ii < 16; ++ii) {
            const float4* w1r = (const float4*)(sW1 + tl * W1S + ii * 16);
            float4 a = w1r[0], b = w1r[1], c = w1r[2], d = w1r[3];
            float s = sB1[tl * 17 + ii];
            s = fmaf(a.x, h0f[0],  s); s = fmaf(a.y, h0f[1],  s);
            s = fmaf(a.z, h0f[2],  s); s = fmaf(a.w, h0f[3],  s);
            s = fmaf(b.x, h0f[4],  s); s = fmaf(b.y, h0f[5],  s);
            s = fmaf(b.z, h0f[6],  s); s = fmaf(b.w, h0f[7],  s);
            s = fmaf(c.x, h0f[8],  s); s = fmaf(c.y, h0f[9],  s);
            s = fmaf(c.z, h0f[10], s); s = fmaf(c.w, h0f[11], s);
            s = fmaf(d.x, h0f[12], s); s = fmaf(d.y, h0f[13], s);
            s = fmaf(d.z, h0f[14], s); s = fmaf(d.w, h0f[15], s);
            h1[ii] = lrelu(s);
        }
        float po[2];
#pragma unroll
        for (int p = 0; p < 2; ++p) {
            const float4* w2r = (const float4*)(sW2 + tl * 36 + p * 16);
            float4 a = w2r[0], b = w2r[1], c = w2r[2], d = w2r[3];
            float s = sB2[tl * 2 + p];
            s = fmaf(a.x, h1[0],  s); s = fmaf(a.y, h1[1],  s);
            s = fmaf(a.z, h1[2],  s); s = fmaf(a.w, h1[3],  s);
            s = fmaf(b.x, h1[4],  s); s = fmaf(b.y, h1[5],  s);
            s = fmaf(b.z, h1[6],  s); s = fmaf(b.w, h1[7],  s);
            s = fmaf(c.x, h1[8],  s); s = fmaf(c.y, h1[9],  s);
            s = fmaf(c.z, h1[10], s); s = fmaf(c.w, h1[11], s);
            s = fmaf(d.x, h1[12], s); s = fmaf(d.y, h1[13], s);
            s = fmaf(d.z, h1[14], s); s = fmaf(d.w, h1[15], s);
            po[p] = s;
        }
        if (tv) {
            float2 o = make_float2(po[0], po[1]);
            *(float2*)(out + ((size_t)(Bbase + k) * D + t) * P) = o;
        }
    }
}

extern "C" void kernel_launch(void* const* d_in, const int* in_sizes, int n_in,
                              void* d_out, int out_size) {
    const float* x  = (const float*)d_in[0];
    const float* M  = (const float*)d_in[1];
    const float* W0 = (const float*)d_in[2];
    const float* W1 = (const float*)d_in[3];
    const float* W2 = (const float*)d_in[4];
    const float* b0 = (const float*)d_in[5];
    const float* b1 = (const float*)d_in[6];
    const float* b2 = (const float*)d_in[7];
    float* out = (float*)d_out;

    constexpr int SMEM_BYTES = SMEM_FLOATS * 4;
    cudaFuncSetAttribute(mlp_kernel, cudaFuncAttributeMaxDynamicSharedMemorySize,
                         SMEM_BYTES);

    transpose_w0_kernel<<<JP, 256>>>(W0);
    transpose_x_kernel<<<dim3(BS / 32, (D + 31) / 32), dim3(32, 8)>>>(x);

    dim3 grid(BS / TB_B, (D + TB_T - 1) / TB_T);   // 256 x 13
    mlp_kernel<<<grid, NTH, SMEM_BYTES>>>(M, W1, W2, b0, b1, b2, out);
}